// round 16
// baseline (speedup 1.0000x reference)
#include <cuda_runtime.h>

#define MM 1000
#define BB 16
#define LL 499500            // MM*(MM-1)/2
#define NODES (BB * MM)
#define RTILE 32             // rows per CTA
#define RPW 4                // rows per warp
#define CTILE 128            // columns per CTA (lane owns 4: l, l+32, l+64, l+96)
#define NTILES 144           // triu 32x128 block tiles covering M=1000
#define NITER 15

// Ping-pong node state (written ONLY by designated CTAs, once per node per pass)
__device__ float g_p2s[2][NODES];
__device__ float g_ds[2][NODES];       // d_t = v_t - p2_t
__device__ float g_dtwA[2][NODES];     // DT(w_t)
__device__ float g_dtp1[NITER][NODES]; // per-iteration DT(p1) accumulators
__device__ float g_S[NITER][BB];       // S_t = sum_nodes d_t  (accumulated in pass t)

__device__ __forceinline__ unsigned long long pol_evict_last() {
    unsigned long long p;
    asm("createpolicy.fractional.L2::evict_last.b64 %0, 1.0;" : "=l"(p));
    return p;
}
__device__ __forceinline__ float ldg_pol(const float* p, unsigned long long pol) {
    float v;
    asm volatile("ld.global.nc.L2::cache_hint.f32 %0, [%1], %2;"
                 : "=f"(v) : "l"(p), "l"(pol));
    return v;
}

__global__ void init_kernel() {
    int x = blockIdx.x * blockDim.x + threadIdx.x;
    if (x < NITER * NODES) ((float*)g_dtp1)[x] = 0.f;
    if (x < NITER * BB) ((float*)g_S)[x] = 0.f;
}

// Per-node update for pass t. All CTAs compute (identical values); only
// designated CTAs store the state for pass t+1.
template<bool FIRST>
__device__ __forceinline__ float2 node_upd(int t, int g, float gn, float alpha,
                                           float c1, float S, bool store) {
    float vt, p2, dtwc;
    if (FIRST) {
        vt = 0.f;
        dtwc = 0.f;
        p2 = -0.5f * sqrtf(fmaxf(4.f * gn * alpha, 1e-8f));
    } else {
        int po = (t - 1) & 1;
        float p2p  = g_p2s[po][g];
        float dp   = g_ds[po][g];
        float dtwp = g_dtwA[po][g];
        float dtp  = g_dtp1[t - 1][g];
        dtwc = (1.f - c1) * dtwp + c1 * dtp + gn * ((float)(MM - 2) * dp + S);
        vt = p2p + gn * (dtp - dtwp);
        float y2 = vt + gn * dtwc;
        float up = fmaxf(fmaf(y2, y2, 4.f * gn * alpha), 1e-8f);
        p2 = 0.5f * (y2 - sqrtf(up));
    }
    if (store) {
        int cc = t & 1;
        g_dtwA[cc][g] = dtwc;
        g_p2s[cc][g]  = p2;
        g_ds[cc][g]   = vt - p2;
    }
    return make_float2(vt, p2);
}

// MODE: 2 dense | 1 column-guard only | 0 full guard (col<MM && c>i)
template<int MODE, bool FIRST>
__device__ __forceinline__ void edge_loop(
    int i0, int c0, int tx,
    const float* __restrict__ zb, const float* __restrict__ wb,
    float* __restrict__ ob, float* __restrict__ dtp1b,
    float c1, float t2,
    const float* s_ngv, const float* s_ngp, const float2* s_ngc,
    float* s_col, float* s_rowp, unsigned long long polZ)
{
    int wd = tx >> 5, l = tx & 31;

    float ngvc[4], ngpc[4];
    bool cok[4];
    #pragma unroll
    for (int k = 0; k < 4; k++) {
        float2 tt = s_ngc[l + 32 * k];
        ngvc[k] = tt.x; ngpc[k] = tt.y;
        cok[k] = (MODE == 2) ? true : (c0 + l + 32 * k < MM);
    }
    float colacc[4] = {0.f, 0.f, 0.f, 0.f};

    int irow = i0 + wd * RPW;
    // e(i,c) = i*(MM-1) - i*(i-1)/2 + c - i - 1
    int e = irow * (MM - 1) - (irow * (irow - 1)) / 2 + c0 + l - irow - 1;

    #pragma unroll
    for (int m = 0; m < RPW; m++) {
        int i = irow + m;
        float ngvi = s_ngv[i - i0];
        float ngpi = s_ngp[i - i0];
        const float* pz = zb + e;
        const float* pw = wb + e;
        float*       po = ob + e;

        bool act[4];
        #pragma unroll
        for (int k = 0; k < 4; k++)
            act[k] = (MODE == 0) ? (cok[k] && (c0 + l + 32 * k > i)) : cok[k];

        float zv[4], wv[4];
        #pragma unroll
        for (int k = 0; k < 4; k++) {
            zv[k] = act[k] ? ldg_pol(pz + 32 * k, polZ) : 0.f;
            wv[k] = (act[k] && !FIRST) ? __ldg(pw + 32 * k) : 0.f;
        }

        float rowacc = 0.f;
        #pragma unroll
        for (int k = 0; k < 4; k++) {
            float y1 = fmaf(c1, wv[k], ngvi + ngvc[k]);
            float p1 = fmaxf(0.f, fmaf(-t2, zv[k], y1));
            if (MODE != 2 && !act[k]) p1 = 0.f;
            float q1 = fmaf(c1, p1, ngpi + ngpc[k]);
            float wn = (wv[k] - y1) + q1;
            if (act[k]) po[32 * k] = wn;
            rowacc += p1;
            colacc[k] += p1;
        }
        s_rowp[l * 33 + (wd * RPW + m)] = rowacc;
        e += MM - 2 - i;
    }

    #pragma unroll
    for (int k = 0; k < 4; k++)
        s_col[wd * CTILE + l + 32 * k] = colacc[k];
    __syncthreads();

    if (tx < RTILE) {
        float a0 = 0.f, a1 = 0.f, a2 = 0.f, a3 = 0.f;
        #pragma unroll
        for (int q = 0; q < 8; q++) {
            a0 += s_rowp[(4 * q + 0) * 33 + tx];
            a1 += s_rowp[(4 * q + 1) * 33 + tx];
            a2 += s_rowp[(4 * q + 2) * 33 + tx];
            a3 += s_rowp[(4 * q + 3) * 33 + tx];
        }
        int i = i0 + tx;
        if (i < MM - 1) atomicAdd(&dtp1b[i], (a0 + a1) + (a2 + a3));
    }
    if (tx < CTILE) {
        float s = 0.f;
        #pragma unroll
        for (int w = 0; w < 8; w++) s += s_col[w * CTILE + tx];
        int c = c0 + tx;
        if (c < MM && c > i0) atomicAdd(&dtp1b[c], s);
    }
}

template<bool FIRST>
__global__ void __launch_bounds__(256, 6) edge_kernel(
    const float* __restrict__ z,
    const float* __restrict__ wprev,
    float* __restrict__ wout,
    const float* __restrict__ gnp,
    const float* __restrict__ alphap,
    const float* __restrict__ betap,
    int t, long long UL)
{
    int tid = blockIdx.x;
    int b = blockIdx.y;
    int tx = threadIdx.x, lane = tx & 31, warp = tx >> 5;

    // tiles: J=0..6 -> 4(J+1) row-tiles each; J=7 -> 32. total 144
    int I, J;
    if (tid < 4)        { J = 0; I = tid; }
    else if (tid < 12)  { J = 1; I = tid - 4; }
    else if (tid < 24)  { J = 2; I = tid - 12; }
    else if (tid < 40)  { J = 3; I = tid - 24; }
    else if (tid < 60)  { J = 4; I = tid - 40; }
    else if (tid < 84)  { J = 5; I = tid - 60; }
    else if (tid < 112) { J = 6; I = tid - 84; }
    else                { J = 7; I = tid - 112; }
    int i0 = I * RTILE;
    int c0 = J * CTILE;
    int mode;
    if (J == 7) mode = (I >= 28) ? 0 : 1;
    else        mode = (I >= 4 * J) ? 0 : 2;
    bool desig = (I == 0);   // designated owner of columns c0..c0+127

    float gn = *gnp, alpha = *alphap, beta = *betap;
    float c1 = 1.f - 2.f * gn * beta;
    float t2 = 2.f * gn;
    unsigned long long polZ = pol_evict_last();

    __shared__ float s_ngv[RTILE];
    __shared__ float s_ngp[RTILE];
    __shared__ float2 s_ngc[CTILE];
    __shared__ float s_col[8 * CTILE];
    __shared__ float s_rowp[32 * 33];
    __shared__ float s_red[4];

    // S_{t-1}: one broadcast scalar load (accumulated during pass t-1)
    float S = FIRST ? 0.f : g_S[t - 1][b];

    // fused node update — values computed by all, stored only by designated
    if (tx < CTILE) {
        int j = c0 + tx;
        float dloc = 0.f;
        if (j < MM) {
            float2 vp = node_upd<FIRST>(t, b * MM + j, gn, alpha, c1, S, desig);
            s_ngc[tx] = make_float2(-gn * vp.x, -gn * vp.y);
            dloc = vp.x - vp.y;
        } else s_ngc[tx] = make_float2(0.f, 0.f);
        // designated CTAs accumulate S_t over their 128 columns
        if (desig) {
            #pragma unroll
            for (int o = 16; o; o >>= 1) dloc += __shfl_xor_sync(0xFFFFFFFFu, dloc, o);
            if (lane == 0) s_red[warp] = dloc;
        }
    } else if (tx < CTILE + RTILE) {
        int r = tx - CTILE;
        int i = i0 + r;
        if (i < MM) {
            float2 vp = node_upd<FIRST>(t, b * MM + i, gn, alpha, c1, S, false);
            s_ngv[r] = -gn * vp.x; s_ngp[r] = -gn * vp.y;
        } else { s_ngv[r] = 0.f; s_ngp[r] = 0.f; }
    }
    __syncthreads();
    if (desig && tx == 0)
        atomicAdd(&g_S[t][b], (s_red[0] + s_red[1]) + (s_red[2] + s_red[3]));

    const float* zb = z + (size_t)b * LL;
    const float* wb = wprev + (size_t)b * UL;
    float*       ob = wout + (size_t)b * UL;
    float* dtp1b = g_dtp1[t] + b * MM;

    if (mode == 2)
        edge_loop<2, FIRST>(i0, c0, tx, zb, wb, ob, dtp1b, c1, t2,
                            s_ngv, s_ngp, s_ngc, s_col, s_rowp, polZ);
    else if (mode == 1)
        edge_loop<1, FIRST>(i0, c0, tx, zb, wb, ob, dtp1b, c1, t2,
                            s_ngv, s_ngp, s_ngc, s_col, s_rowp, polZ);
    else
        edge_loop<0, FIRST>(i0, c0, tx, zb, wb, ob, dtp1b, c1, t2,
                            s_ngv, s_ngp, s_ngc, s_col, s_rowp, polZ);
}

extern "C" void kernel_launch(void* const* d_in, const int* in_sizes, int n_in,
                              void* d_out, int out_size) {
    const float* z     = (const float*)d_in[0];
    const float* gn    = (const float*)d_in[1];
    const float* alpha = (const float*)d_in[2];
    const float* beta  = (const float*)d_in[3];
    float* out = (float*)d_out;
    int U = out_size / (BB * LL);
    if (U <= 0 || U > NITER) U = NITER;
    long long UL = (long long)U * LL;

    init_kernel<<<(NITER * NODES + 255) / 256, 256>>>();

    for (int t = 0; t < U; t++) {
        const float* wprev = (t == 0) ? out : (out + (size_t)(t - 1) * LL);
        float*       wout  = out + (size_t)t * LL;
        if (t == 0)
            edge_kernel<true><<<dim3(NTILES, BB), 256>>>(z, wprev, wout, gn, alpha, beta, 0, UL);
        else
            edge_kernel<false><<<dim3(NTILES, BB), 256>>>(z, wprev, wout, gn, alpha, beta, t, UL);
    }
}

// round 17
// speedup vs baseline: 1.1308x; 1.1308x over previous
#include <cuda_runtime.h>

#define MM 1000
#define BB 16
#define LL 499500            // MM*(MM-1)/2
#define NODES (BB * MM)
#define RTILE 32             // rows per CTA
#define RPW 4                // rows per warp
#define CTILE 128            // columns per CTA (lane owns 4: l, l+32, l+64, l+96)
#define NTILES 144           // triu 32x128 block tiles covering M=1000
#define NITER 15
#define TOTW (NTILES * BB)   // total work items per pass

// Ping-pong node state (written ONLY by designated CTAs, once per node per pass)
__device__ float g_p2s[2][NODES];
__device__ float g_ds[2][NODES];       // d_t = v_t - p2_t
__device__ float g_dtwA[2][NODES];     // DT(w_t)
__device__ float g_dtp1[NITER][NODES]; // per-iteration DT(p1) accumulators
__device__ float g_S[NITER][BB];       // S_t = sum_nodes d_t  (accumulated in pass t)

__device__ __forceinline__ unsigned long long pol_evict_last() {
    unsigned long long p;
    asm("createpolicy.fractional.L2::evict_last.b64 %0, 1.0;" : "=l"(p));
    return p;
}
__device__ __forceinline__ float ldg_pol(const float* p, unsigned long long pol) {
    float v;
    asm volatile("ld.global.nc.L2::cache_hint.f32 %0, [%1], %2;"
                 : "=f"(v) : "l"(p), "l"(pol));
    return v;
}

__global__ void init_kernel() {
    int x = blockIdx.x * blockDim.x + threadIdx.x;
    if (x < NITER * NODES) ((float*)g_dtp1)[x] = 0.f;
    if (x < NITER * BB) ((float*)g_S)[x] = 0.f;
}

// Per-node update for pass t. All CTAs compute (identical values); only
// designated CTAs store the state for pass t+1.
template<bool FIRST>
__device__ __forceinline__ float2 node_upd(int t, int g, float gn, float alpha,
                                           float c1, float S, bool store) {
    float vt, p2, dtwc;
    if (FIRST) {
        vt = 0.f;
        dtwc = 0.f;
        p2 = -0.5f * sqrtf(fmaxf(4.f * gn * alpha, 1e-8f));
    } else {
        int po = (t - 1) & 1;
        float p2p  = g_p2s[po][g];
        float dp   = g_ds[po][g];
        float dtwp = g_dtwA[po][g];
        float dtp  = g_dtp1[t - 1][g];
        dtwc = (1.f - c1) * dtwp + c1 * dtp + gn * ((float)(MM - 2) * dp + S);
        vt = p2p + gn * (dtp - dtwp);
        float y2 = vt + gn * dtwc;
        float up = fmaxf(fmaf(y2, y2, 4.f * gn * alpha), 1e-8f);
        p2 = 0.5f * (y2 - sqrtf(up));
    }
    if (store) {
        int cc = t & 1;
        g_dtwA[cc][g] = dtwc;
        g_p2s[cc][g]  = p2;
        g_ds[cc][g]   = vt - p2;
    }
    return make_float2(vt, p2);
}

// MODE: 2 dense | 1 column-guard only | 0 full guard (col<MM && c>i)
template<int MODE, bool FIRST>
__device__ __forceinline__ void edge_loop(
    int i0, int c0, int tx,
    const float* __restrict__ zb, const float* __restrict__ wb,
    float* __restrict__ ob, float* __restrict__ dtp1b,
    float c1, float t2,
    const float* s_ngv, const float* s_ngp, const float2* s_ngc,
    float* s_col, float* s_rowp, unsigned long long polZ)
{
    int wd = tx >> 5, l = tx & 31;

    float ngvc[4], ngpc[4];
    bool cok[4];
    #pragma unroll
    for (int k = 0; k < 4; k++) {
        float2 tt = s_ngc[l + 32 * k];
        ngvc[k] = tt.x; ngpc[k] = tt.y;
        cok[k] = (MODE == 2) ? true : (c0 + l + 32 * k < MM);
    }
    float colacc[4] = {0.f, 0.f, 0.f, 0.f};

    int irow = i0 + wd * RPW;
    // e(i,c) = i*(MM-1) - i*(i-1)/2 + c - i - 1
    int e = irow * (MM - 1) - (irow * (irow - 1)) / 2 + c0 + l - irow - 1;

    #pragma unroll
    for (int m = 0; m < RPW; m++) {
        int i = irow + m;
        float ngvi = s_ngv[i - i0];
        float ngpi = s_ngp[i - i0];
        const float* pz = zb + e;
        const float* pw = wb + e;
        float*       po = ob + e;

        bool act[4];
        #pragma unroll
        for (int k = 0; k < 4; k++)
            act[k] = (MODE == 0) ? (cok[k] && (c0 + l + 32 * k > i)) : cok[k];

        float zv[4], wv[4];
        #pragma unroll
        for (int k = 0; k < 4; k++) {
            zv[k] = act[k] ? ldg_pol(pz + 32 * k, polZ) : 0.f;
            wv[k] = (act[k] && !FIRST) ? __ldg(pw + 32 * k) : 0.f;
        }

        float rowacc = 0.f;
        #pragma unroll
        for (int k = 0; k < 4; k++) {
            float y1 = fmaf(c1, wv[k], ngvi + ngvc[k]);
            float p1 = fmaxf(0.f, fmaf(-t2, zv[k], y1));
            if (MODE != 2 && !act[k]) p1 = 0.f;
            float q1 = fmaf(c1, p1, ngpi + ngpc[k]);
            float wn = (wv[k] - y1) + q1;
            if (act[k]) po[32 * k] = wn;
            rowacc += p1;
            colacc[k] += p1;
        }
        s_rowp[l * 33 + (wd * RPW + m)] = rowacc;
        e += MM - 2 - i;
    }

    #pragma unroll
    for (int k = 0; k < 4; k++)
        s_col[wd * CTILE + l + 32 * k] = colacc[k];
    __syncthreads();

    if (tx < RTILE) {
        float a0 = 0.f, a1 = 0.f, a2 = 0.f, a3 = 0.f;
        #pragma unroll
        for (int q = 0; q < 8; q++) {
            a0 += s_rowp[(4 * q + 0) * 33 + tx];
            a1 += s_rowp[(4 * q + 1) * 33 + tx];
            a2 += s_rowp[(4 * q + 2) * 33 + tx];
            a3 += s_rowp[(4 * q + 3) * 33 + tx];
        }
        int i = i0 + tx;
        if (i < MM - 1) atomicAdd(&dtp1b[i], (a0 + a1) + (a2 + a3));
    }
    if (tx < CTILE) {
        float s = 0.f;
        #pragma unroll
        for (int w = 0; w < 8; w++) s += s_col[w * CTILE + tx];
        int c = c0 + tx;
        if (c < MM && c > i0) atomicAdd(&dtp1b[c], s);
    }
}

template<bool FIRST, bool REV>
__global__ void __launch_bounds__(256, 5) edge_kernel(
    const float* __restrict__ z,
    const float* __restrict__ wprev,
    float* __restrict__ wout,
    const float* __restrict__ gnp,
    const float* __restrict__ alphap,
    const float* __restrict__ betap,
    int t, long long UL)
{
    // serpentine: odd passes process work items in reverse so pass t+1 first
    // touches the lines pass t wrote last (hot in L2)
    int linear = blockIdx.y * NTILES + blockIdx.x;
    if (REV) linear = TOTW - 1 - linear;
    int b   = linear / NTILES;
    int tid = linear % NTILES;
    int tx = threadIdx.x, lane = tx & 31, warp = tx >> 5;

    // tiles: J=0..6 -> 4(J+1) row-tiles each; J=7 -> 32. total 144
    int I, J;
    if (tid < 4)        { J = 0; I = tid; }
    else if (tid < 12)  { J = 1; I = tid - 4; }
    else if (tid < 24)  { J = 2; I = tid - 12; }
    else if (tid < 40)  { J = 3; I = tid - 24; }
    else if (tid < 60)  { J = 4; I = tid - 40; }
    else if (tid < 84)  { J = 5; I = tid - 60; }
    else if (tid < 112) { J = 6; I = tid - 84; }
    else                { J = 7; I = tid - 112; }
    int i0 = I * RTILE;
    int c0 = J * CTILE;
    int mode;
    if (J == 7) mode = (I >= 28) ? 0 : 1;
    else        mode = (I >= 4 * J) ? 0 : 2;
    bool desig = (I == 0);   // designated owner of columns c0..c0+127

    float gn = *gnp, alpha = *alphap, beta = *betap;
    float c1 = 1.f - 2.f * gn * beta;
    float t2 = 2.f * gn;
    unsigned long long polZ = pol_evict_last();

    __shared__ float s_ngv[RTILE];
    __shared__ float s_ngp[RTILE];
    __shared__ float2 s_ngc[CTILE];
    __shared__ float s_col[8 * CTILE];
    __shared__ float s_rowp[32 * 33];
    __shared__ float s_red[4];

    // S_{t-1}: one broadcast scalar load (accumulated during pass t-1)
    float S = FIRST ? 0.f : g_S[t - 1][b];

    // fused node update — values computed by all, stored only by designated
    if (tx < CTILE) {
        int j = c0 + tx;
        float dloc = 0.f;
        if (j < MM) {
            float2 vp = node_upd<FIRST>(t, b * MM + j, gn, alpha, c1, S, desig);
            s_ngc[tx] = make_float2(-gn * vp.x, -gn * vp.y);
            dloc = vp.x - vp.y;
        } else s_ngc[tx] = make_float2(0.f, 0.f);
        // designated CTAs accumulate S_t over their 128 columns
        if (desig) {
            #pragma unroll
            for (int o = 16; o; o >>= 1) dloc += __shfl_xor_sync(0xFFFFFFFFu, dloc, o);
            if (lane == 0) s_red[warp] = dloc;
        }
    } else if (tx < CTILE + RTILE) {
        int r = tx - CTILE;
        int i = i0 + r;
        if (i < MM) {
            float2 vp = node_upd<FIRST>(t, b * MM + i, gn, alpha, c1, S, false);
            s_ngv[r] = -gn * vp.x; s_ngp[r] = -gn * vp.y;
        } else { s_ngv[r] = 0.f; s_ngp[r] = 0.f; }
    }
    __syncthreads();
    if (desig && tx == 0)
        atomicAdd(&g_S[t][b], (s_red[0] + s_red[1]) + (s_red[2] + s_red[3]));

    const float* zb = z + (size_t)b * LL;
    const float* wb = wprev + (size_t)b * UL;
    float*       ob = wout + (size_t)b * UL;
    float* dtp1b = g_dtp1[t] + b * MM;

    if (mode == 2)
        edge_loop<2, FIRST>(i0, c0, tx, zb, wb, ob, dtp1b, c1, t2,
                            s_ngv, s_ngp, s_ngc, s_col, s_rowp, polZ);
    else if (mode == 1)
        edge_loop<1, FIRST>(i0, c0, tx, zb, wb, ob, dtp1b, c1, t2,
                            s_ngv, s_ngp, s_ngc, s_col, s_rowp, polZ);
    else
        edge_loop<0, FIRST>(i0, c0, tx, zb, wb, ob, dtp1b, c1, t2,
                            s_ngv, s_ngp, s_ngc, s_col, s_rowp, polZ);
}

extern "C" void kernel_launch(void* const* d_in, const int* in_sizes, int n_in,
                              void* d_out, int out_size) {
    const float* z     = (const float*)d_in[0];
    const float* gn    = (const float*)d_in[1];
    const float* alpha = (const float*)d_in[2];
    const float* beta  = (const float*)d_in[3];
    float* out = (float*)d_out;
    int U = out_size / (BB * LL);
    if (U <= 0 || U > NITER) U = NITER;
    long long UL = (long long)U * LL;

    init_kernel<<<(NITER * NODES + 255) / 256, 256>>>();

    for (int t = 0; t < U; t++) {
        const float* wprev = (t == 0) ? out : (out + (size_t)(t - 1) * LL);
        float*       wout  = out + (size_t)t * LL;
        if (t == 0)
            edge_kernel<true, false><<<dim3(NTILES, BB), 256>>>(z, wprev, wout, gn, alpha, beta, 0, UL);
        else if (t & 1)
            edge_kernel<false, true><<<dim3(NTILES, BB), 256>>>(z, wprev, wout, gn, alpha, beta, t, UL);
        else
            edge_kernel<false, false><<<dim3(NTILES, BB), 256>>>(z, wprev, wout, gn, alpha, beta, t, UL);
    }
}